// round 16
// baseline (speedup 1.0000x reference)
#include <cuda_runtime.h>
#include <cuda_fp16.h>
#include <cstdint>

#define BATCH   8
#define TSTEPS  12
#define CIN_X   5
#define HID     16
#define IMG     256
#define NTHREADS 512

/* smem: A (fp16) [512 rows][64 f16] = 65536 B; B (fp16) 3 dy x 8192 B */
#define SM_A       0
#define SM_B(dy)   (65536 + (dy) * 8192)
#define SMEM_TOTAL 90112               /* 88 KB -> 2 CTAs/SM */
#define STAGE_STRIDE 68                /* f32 stage: 256*68*4 = 69632 <= total */

/* h state: [2][b][pix][ch] fp16; c: [b][pix][ch] fp32 */
__device__ __half g_hh[2][BATCH * IMG * IMG * HID];
__device__ float  g_c [BATCH * IMG * IMG * HID];
__device__ uint4  g_B [3 * 512];
/* im2col-x: [b][t][pix][16 halves] = 2 uint4 per pixel (k48..63 slots of A) */
__device__ uint4  g_xi[BATCH * TSTEPS * IMG * IMG * 2];

__device__ __forceinline__ uint32_t smem_u32(const void* p) {
    uint32_t a;
    asm("{ .reg .u64 t; cvta.to.shared.u64 t, %1; cvt.u32.u64 %0, t; }" : "=r"(a) : "l"(p));
    return a;
}
__device__ __forceinline__ void ldsm4(uint32_t* r, uint32_t addr) {
    asm volatile("ldmatrix.sync.aligned.m8n8.x4.shared.b16 {%0,%1,%2,%3}, [%4];"
                 : "=r"(r[0]), "=r"(r[1]), "=r"(r[2]), "=r"(r[3]) : "r"(addr));
}
__device__ __forceinline__ void mma16816(float* c, const uint32_t* a, uint32_t b0, uint32_t b1) {
    asm volatile("mma.sync.aligned.m16n8k16.row.col.f32.f16.f16.f32 "
                 "{%0,%1,%2,%3}, {%4,%5,%6,%7}, {%8,%9}, {%0,%1,%2,%3};"
                 : "+f"(c[0]), "+f"(c[1]), "+f"(c[2]), "+f"(c[3])
                 : "r"(a[0]), "r"(a[1]), "r"(a[2]), "r"(a[3]), "r"(b0), "r"(b1));
}
__device__ __forceinline__ float sig_(float x)  { return 1.0f / (1.0f + __expf(-x)); }
__device__ __forceinline__ float tanh_(float x) { return 2.0f / (1.0f + __expf(-2.0f * x)) - 1.0f; }

/* K ordering (unchanged from R15): k<48: h tap dx=k>>4, ch=k&15 (in-ch 5+ch)
   k in [48,63): x tap dx=(k-48)/5, ch=(k-48)%5 ; k=63 pad */
__device__ __forceinline__ float wk(const float* Wc, int n, int dy, int k) {
    if (k < 48) { int dx = k >> 4;  int ch = k & 15;       return Wc[n * 189 + (5 + ch) * 9 + dy * 3 + dx]; }
    if (k < 63) { int q = k - 48;   int dx = q / 5;
                  int ch = q - 5 * dx;                     return Wc[n * 189 + ch * 9 + dy * 3 + dx]; }
    return 0.0f;
}

/* Precompute B (fp16) swizzled smem image. 192 threads: (dy, n). */
__global__ void build_B_kernel(const float* __restrict__ Wc)
{
    const int tid = threadIdx.x;
    if (tid >= 192) return;
    const int dy = tid >> 6;
    const int n  = tid & 63;
    #pragma unroll
    for (int i = 0; i < 8; ++i) {
        uint32_t hp[4];
        #pragma unroll
        for (int jj = 0; jj < 4; ++jj) {
            float v0 = wk(Wc, n, dy, i * 8 + 2 * jj);
            float v1 = wk(Wc, n, dy, i * 8 + 2 * jj + 1);
            hp[jj] = (uint32_t)__half_as_ushort(__float2half_rn(v0)) |
                     ((uint32_t)__half_as_ushort(__float2half_rn(v1)) << 16);
        }
        uint32_t off = (uint32_t)(n * 128 + i * 16);
        off ^= (uint32_t)((n & 7) << 4);
        g_B[(dy * 8192 + (int)off) >> 4] = make_uint4(hp[0], hp[1], hp[2], hp[3]);
    }
}

/* Precompute im2col-x: for each (b,t,pixel), the 15 fp16 x taps + pad. */
__global__ void prep_xi_kernel(const float* __restrict__ xall)
{
    const int total = BATCH * TSTEPS * IMG * IMG;
    int p = blockIdx.x * blockDim.x + threadIdx.x;
    if (p >= total) return;
    const int bt  = p >> 16;            /* (b*TSTEPS+t) */
    const int pix = p & 65535;
    const int y   = pix >> 8;
    const int x   = pix & 255;
    unsigned short hs[16];
    hs[15] = 0;
    #pragma unroll
    for (int dx = 0; dx < 3; ++dx) {
        const int gx = x - 1 + dx;
        const bool ok = ((unsigned)gx < IMG);
        #pragma unroll
        for (int ch = 0; ch < CIN_X; ++ch) {
            float v = ok ? xall[((bt * CIN_X + ch) << 16) + (y << 8) + gx] : 0.0f;
            hs[dx * 5 + ch] = __half_as_ushort(__float2half_rn(v));
        }
    }
    uint4 q0, q1;
    uint32_t* w = (uint32_t*)&q0;
    #pragma unroll
    for (int e = 0; e < 4; ++e)
        w[e] = (uint32_t)hs[2 * e] | ((uint32_t)hs[2 * e + 1] << 16);
    uint32_t* w1 = (uint32_t*)&q1;
    #pragma unroll
    for (int e = 0; e < 4; ++e)
        w1[e] = (uint32_t)hs[8 + 2 * e] | ((uint32_t)hs[9 + 2 * e] << 16);
    g_xi[p * 2]     = q0;
    g_xi[p * 2 + 1] = q1;
}

/* Fused ConvLSTM step: single-pass fp16 mma.sync implicit GEMM.
   CTA: (b, y0=2*by, x0) -> 2 output rows x 128 px (M=256). 16 warps (8m x 2n).
   A row build = 8 aligned LDG.128 + 8 STS.128 (h is [pix][ch]; x is im2col'ed). */
__global__ void __launch_bounds__(NTHREADS, 2)
lstm_step_kernel(const float* __restrict__ bc, int t)
{
    extern __shared__ char smem[];
    const uint32_t sb = smem_u32(smem);
    float* s_stage = (float*)smem;

    const int tid  = threadIdx.x;
    const int wid  = tid >> 5;
    const int lane = tid & 31;
    const int b  = blockIdx.z;
    const int y0 = blockIdx.y << 1;
    const int x0 = blockIdx.x << 7;
    const int first = (t == 0);

    const __half* hh_prev = g_hh[t & 1];
    __half*       hh_next = g_hh[(t + 1) & 1];

    /* ---- copy B image (24 KB) ---- */
    {
        uint4* dst = (uint4*)(smem + SM_B(0));
        #pragma unroll 1
        for (int i = tid; i < 1536; i += NTHREADS) dst[i] = g_B[i];
    }
    /* ---- build A: one (strip, px) per thread; A row index = tid ---- */
    {
        const int r  = tid >> 7;            /* input strip 0..3 */
        const int m  = tid & 127;
        const int gy = y0 - 1 + r;
        const bool rowok = ((unsigned)gy < IMG);
        const int gx = x0 + m;              /* center pixel x, always in range */
        uint4 q[8];
        /* h taps: 3 neighbor pixels x 16 ch, 2 x 16B each */
        #pragma unroll
        for (int dx = 0; dx < 3; ++dx) {
            const int nx = gx - 1 + dx;
            uint4 lo = make_uint4(0, 0, 0, 0), hi = make_uint4(0, 0, 0, 0);
            if (rowok && (unsigned)nx < IMG && !first) {
                const uint4* hp = (const uint4*)(hh_prev +
                    ((size_t)((b << 16) + (gy << 8) + nx)) * HID);
                lo = hp[0]; hi = hp[1];
            }
            q[dx * 2]     = lo;
            q[dx * 2 + 1] = hi;
        }
        /* x taps: 2 x 16B from the precomputed im2col plane */
        if (rowok) {
            const uint4* xp = g_xi +
                ((size_t)(((b * TSTEPS + t) << 16) + (gy << 8) + gx)) * 2;
            q[6] = xp[0];
            q[7] = xp[1];
        } else {
            q[6] = make_uint4(0, 0, 0, 0);
            q[7] = make_uint4(0, 0, 0, 0);
        }
        #pragma unroll
        for (int qi = 0; qi < 8; ++qi) {
            uint32_t off = (uint32_t)(tid * 128 + qi * 16);
            off ^= (uint32_t)((tid & 7) << 4);
            *(uint4*)(smem + SM_A + off) = q[qi];
        }
    }
    __syncthreads();

    /* ---- mainloop: 12 iters x (4 ldsm + 8 mma) ---- */
    const int wm = wid >> 1;
    const int wn = wid & 1;
    const int m_base = wm * 32;
    const int n_base = wn * 32;
    const int j  = lane >> 3;
    const int rr = lane & 7;

    uint32_t offA[2], offB[2];
    #pragma unroll
    for (int mt = 0; mt < 2; ++mt) {
        const int row = m_base + mt * 16 + (j & 1) * 8 + rr;
        const int c16 = j >> 1;
        offA[mt] = (uint32_t)(row * 128 + ((c16 << 4) ^ ((row & 7) << 4)));
    }
    #pragma unroll
    for (int nb = 0; nb < 2; ++nb) {
        const int row = n_base + nb * 16 + (j >> 1) * 8 + rr;
        const int c16 = j & 1;
        offB[nb] = (uint32_t)(row * 128 + ((c16 << 4) ^ ((row & 7) << 4)));
    }

    float acc[8][4];
    #pragma unroll
    for (int q = 0; q < 8; ++q)
        #pragma unroll
        for (int e = 0; e < 4; ++e) acc[q][e] = 0.0f;

    #pragma unroll
    for (int it = 0; it < 12; ++it) {
        const int dy = it >> 2;
        const uint32_t kx = (uint32_t)((it & 3) << 5);
        const uint32_t Ab = sb + SM_A + (uint32_t)(dy * 16384);
        uint32_t a0[4], a1[4], b0[4], b1[4];
        ldsm4(a0, Ab + (offA[0] ^ kx));
        ldsm4(a1, Ab + (offA[1] ^ kx));
        ldsm4(b0, sb + SM_B(dy) + (offB[0] ^ kx));
        ldsm4(b1, sb + SM_B(dy) + (offB[1] ^ kx));
        mma16816(acc[0], a0, b0[0], b0[1]);
        mma16816(acc[1], a0, b0[2], b0[3]);
        mma16816(acc[2], a0, b1[0], b1[1]);
        mma16816(acc[3], a0, b1[2], b1[3]);
        mma16816(acc[4], a1, b0[0], b0[1]);
        mma16816(acc[5], a1, b0[2], b0[3]);
        mma16816(acc[6], a1, b1[0], b1[1]);
        mma16816(acc[7], a1, b1[2], b1[3]);
    }
    __syncthreads();

    /* ---- stage acc -> smem f32 [256][68] ---- */
    {
        const int g = lane >> 2;
        const int q = lane & 3;
        #pragma unroll
        for (int mt = 0; mt < 2; ++mt)
            #pragma unroll
            for (int nb = 0; nb < 4; ++nb) {
                const int m = m_base + mt * 16 + g;
                const int n = n_base + nb * 8 + 2 * q;
                float* p0 = s_stage + m * STAGE_STRIDE + n;
                p0[0] = acc[mt * 4 + nb][0];
                p0[1] = acc[mt * 4 + nb][1];
                float* p1 = p0 + 8 * STAGE_STRIDE;
                p1[0] = acc[mt * 4 + nb][2];
                p1[1] = acc[mt * 4 + nb][3];
            }
    }
    __syncthreads();

    /* ---- epilogue: 2 threads/pixel x 8 ch ---- */
    {
        const int pl   = tid >> 1;
        const int half = tid & 1;
        const float* sp = s_stage + pl * STAGE_STRIDE + half * 8;
        const int pix = ((y0 + (pl >> 7)) << 8) + x0 + (pl & 127);
        const int base = ((b << 16) + pix) * HID + half * 8;

        float4 iva = *(const float4*)(sp);      float4 ivb = *(const float4*)(sp + 4);
        float4 fva = *(const float4*)(sp + 16); float4 fvb = *(const float4*)(sp + 20);
        float4 ova = *(const float4*)(sp + 32); float4 ovb = *(const float4*)(sp + 36);
        float4 gva = *(const float4*)(sp + 48); float4 gvb = *(const float4*)(sp + 52);
        float iv[8] = {iva.x, iva.y, iva.z, iva.w, ivb.x, ivb.y, ivb.z, ivb.w};
        float fv[8] = {fva.x, fva.y, fva.z, fva.w, fvb.x, fvb.y, fvb.z, fvb.w};
        float ov[8] = {ova.x, ova.y, ova.z, ova.w, ovb.x, ovb.y, ovb.z, ovb.w};
        float gv[8] = {gva.x, gva.y, gva.z, gva.w, gvb.x, gvb.y, gvb.z, gvb.w};

        float cold[8];
        if (!first) {
            float4 c0 = *(const float4*)(g_c + base);
            float4 c1 = *(const float4*)(g_c + base + 4);
            cold[0] = c0.x; cold[1] = c0.y; cold[2] = c0.z; cold[3] = c0.w;
            cold[4] = c1.x; cold[5] = c1.y; cold[6] = c1.z; cold[7] = c1.w;
        } else {
            #pragma unroll
            for (int e = 0; e < 8; ++e) cold[e] = 0.0f;
        }

        float cn[8];
        unsigned short hn[8];
        #pragma unroll
        for (int e = 0; e < 8; ++e) {
            const int hid = half * 8 + e;
            const float i = sig_(iv[e] + bc[hid]);
            const float f = sig_(fv[e] + bc[hid + 16]);
            const float o = sig_(ov[e] + bc[hid + 32]);
            const float g = tanh_(gv[e] + bc[hid + 48]);
            const float c = f * cold[e] + i * g;
            cn[e] = c;
            hn[e] = __half_as_ushort(__float2half_rn(o * tanh_(c)));
        }
        *(float4*)(g_c + base)     = make_float4(cn[0], cn[1], cn[2], cn[3]);
        *(float4*)(g_c + base + 4) = make_float4(cn[4], cn[5], cn[6], cn[7]);
        uint4 hv;
        hv.x = (uint32_t)hn[0] | ((uint32_t)hn[1] << 16);
        hv.y = (uint32_t)hn[2] | ((uint32_t)hn[3] << 16);
        hv.z = (uint32_t)hn[4] | ((uint32_t)hn[5] << 16);
        hv.w = (uint32_t)hn[6] | ((uint32_t)hn[7] << 16);
        *(uint4*)(hh_next + base) = hv;
    }
}

/* Final 1x1 conv over [pix][ch] fp16 h_last. 4 px per thread. */
__global__ void final_conv_kernel(const float* __restrict__ Wf,
                                  const float* __restrict__ bfin,
                                  float* __restrict__ out)
{
    const int total4 = BATCH * IMG * IMG / 4;
    int p4 = blockIdx.x * blockDim.x + threadIdx.x;
    if (p4 >= total4) return;
    const __half* h = g_hh[TSTEPS & 1];
    const int b    = p4 >> 14;
    const int pix0 = (p4 & 16383) * 4;
    float w[HID];
    #pragma unroll
    for (int jj = 0; jj < HID; ++jj) w[jj] = Wf[jj];
    const float bv = bfin[0];
    float a[4];
    #pragma unroll
    for (int p = 0; p < 4; ++p) {
        const __half2* hp = (const __half2*)(h + ((size_t)((b << 16) + pix0 + p)) * HID);
        float s = bv;
        #pragma unroll
        for (int q = 0; q < 8; ++q) {
            float2 f2 = __half22float2(hp[q]);
            s += w[2 * q] * f2.x + w[2 * q + 1] * f2.y;
        }
        a[p] = s;
    }
    ((float4*)out)[p4] = make_float4(a[0], a[1], a[2], a[3]);
}

extern "C" void kernel_launch(void* const* d_in, const int* in_sizes, int n_in,
                              void* d_out, int out_size)
{
    const float* x  = (const float*)d_in[0];
    const float* Wc = (const float*)d_in[1];
    const float* bc = (const float*)d_in[2];
    const float* Wf = (const float*)d_in[3];
    const float* bf = (const float*)d_in[4];
    float* out = (float*)d_out;

    cudaFuncSetAttribute(lstm_step_kernel,
                         cudaFuncAttributeMaxDynamicSharedMemorySize, SMEM_TOTAL);

    build_B_kernel<<<1, 192>>>(Wc);
    const int xtotal = BATCH * TSTEPS * IMG * IMG;
    prep_xi_kernel<<<(xtotal + 255) / 256, 256>>>(x);

    dim3 grid(IMG / 128, IMG / 2, BATCH);   /* 2048 CTAs */
    for (int t = 0; t < TSTEPS; ++t)
        lstm_step_kernel<<<grid, NTHREADS, SMEM_TOTAL>>>(bc, t);

    const int total4 = BATCH * IMG * IMG / 4;
    final_conv_kernel<<<(total4 + 511) / 512, 512>>>(Wf, bf, out);
}

// round 17
// speedup vs baseline: 1.3207x; 1.3207x over previous
#include <cuda_runtime.h>
#include <cuda_fp16.h>
#include <cstdint>

#define BATCH   8
#define TSTEPS  12
#define CIN_X   5
#define HID     16
#define IMG     256
#define NTHREADS 512

/* smem: A (fp16) [512 rows][64 f16] = 65536 B; B (fp16) 3 dy x 8192 B */
#define SM_A       0
#define SM_B(dy)   (65536 + (dy) * 8192)
#define SMEM_TOTAL 90112               /* 88 KB -> 2 CTAs/SM */

/* h state: [2][b][pix][ch] fp16; c: [b][pix][ch] fp32 */
__device__ __half g_hh[2][BATCH * IMG * IMG * HID];
__device__ float  g_c [BATCH * IMG * IMG * HID];
__device__ uint4  g_B [3 * 512];

__device__ __forceinline__ uint32_t smem_u32(const void* p) {
    uint32_t a;
    asm("{ .reg .u64 t; cvta.to.shared.u64 t, %1; cvt.u32.u64 %0, t; }" : "=r"(a) : "l"(p));
    return a;
}
__device__ __forceinline__ void ldsm4(uint32_t* r, uint32_t addr) {
    asm volatile("ldmatrix.sync.aligned.m8n8.x4.shared.b16 {%0,%1,%2,%3}, [%4];"
                 : "=r"(r[0]), "=r"(r[1]), "=r"(r[2]), "=r"(r[3]) : "r"(addr));
}
__device__ __forceinline__ void mma16816(float* c, const uint32_t* a, uint32_t b0, uint32_t b1) {
    asm volatile("mma.sync.aligned.m16n8k16.row.col.f32.f16.f16.f32 "
                 "{%0,%1,%2,%3}, {%4,%5,%6,%7}, {%8,%9}, {%0,%1,%2,%3};"
                 : "+f"(c[0]), "+f"(c[1]), "+f"(c[2]), "+f"(c[3])
                 : "r"(a[0]), "r"(a[1]), "r"(a[2]), "r"(a[3]), "r"(b0), "r"(b1));
}
__device__ __forceinline__ float sig_(float x)  { return 1.0f / (1.0f + __expf(-x)); }
__device__ __forceinline__ float tanh_(float x) { return 2.0f / (1.0f + __expf(-2.0f * x)) - 1.0f; }

/* K ordering (as R15): k<48: h tap dx=k>>4, ch=k&15 (in-ch 5+ch)
   k in [48,63): x tap dx=(k-48)/5, ch=(k-48)%5 ; k=63 pad */
__device__ __forceinline__ float wk(const float* Wc, int n, int dy, int k) {
    if (k < 48) { int dx = k >> 4;  int ch = k & 15;       return Wc[n * 189 + (5 + ch) * 9 + dy * 3 + dx]; }
    if (k < 63) { int q = k - 48;   int dx = q / 5;
                  int ch = q - 5 * dx;                     return Wc[n * 189 + ch * 9 + dy * 3 + dx]; }
    return 0.0f;
}

/* Precompute B (fp16) swizzled smem image with PERMUTED columns:
   column c -> gate = (c&31)>>3, hid = (c>>5)*8 + (c&7); out_ch = gate*16+hid.
   This makes each mma thread hold all 4 gates of its (pixel, hid) cells. */
__global__ void build_B_kernel(const float* __restrict__ Wc)
{
    const int tid = threadIdx.x;
    if (tid >= 192) return;
    const int dy = tid >> 6;
    const int nc = tid & 63;                       /* B row = column slot */
    const int gate = (nc & 31) >> 3;
    const int hid  = ((nc >> 5) << 3) + (nc & 7);
    const int n    = gate * 16 + hid;              /* original output channel */
    #pragma unroll
    for (int i = 0; i < 8; ++i) {
        uint32_t hp[4];
        #pragma unroll
        for (int jj = 0; jj < 4; ++jj) {
            float v0 = wk(Wc, n, dy, i * 8 + 2 * jj);
            float v1 = wk(Wc, n, dy, i * 8 + 2 * jj + 1);
            hp[jj] = (uint32_t)__half_as_ushort(__float2half_rn(v0)) |
                     ((uint32_t)__half_as_ushort(__float2half_rn(v1)) << 16);
        }
        uint32_t off = (uint32_t)(nc * 128 + i * 16);
        off ^= (uint32_t)((nc & 7) << 4);
        g_B[(dy * 8192 + (int)off) >> 4] = make_uint4(hp[0], hp[1], hp[2], hp[3]);
    }
}

/* Fused ConvLSTM step: single-pass fp16 mma.sync implicit GEMM.
   CTA: (b, y0=2*by, x0) -> 2 output rows x 128 px (M=256). 16 warps (8m x 2n).
   Permuted B -> epilogue entirely in registers (no stage, no 2nd sync). */
__global__ void __launch_bounds__(NTHREADS, 2)
lstm_step_kernel(const float* __restrict__ xall, const float* __restrict__ bc, int t)
{
    extern __shared__ char smem[];
    const uint32_t sb = smem_u32(smem);

    const int tid  = threadIdx.x;
    const int wid  = tid >> 5;
    const int lane = tid & 31;
    const int b  = blockIdx.z;
    const int y0 = blockIdx.y << 1;
    const int x0 = blockIdx.x << 7;
    const int first = (t == 0);

    const __half* hh_prev = g_hh[t & 1];
    __half*       hh_next = g_hh[(t + 1) & 1];

    /* ---- copy B image (24 KB) ---- */
    {
        uint4* dst = (uint4*)(smem + SM_B(0));
        #pragma unroll 1
        for (int i = tid; i < 1536; i += NTHREADS) dst[i] = g_B[i];
    }
    /* ---- build A: one (strip, px) per thread; A row index = tid ---- */
    {
        const int r  = tid >> 7;            /* input strip 0..3 */
        const int m  = tid & 127;
        const int gy = y0 - 1 + r;
        const bool rowok = ((unsigned)gy < IMG);
        uint4 q[8];
        /* h taps: 3 neighbor pixels x 16 ch, 2 x 16B each */
        #pragma unroll
        for (int dx = 0; dx < 3; ++dx) {
            const int nx = x0 + m - 1 + dx;
            uint4 lo = make_uint4(0, 0, 0, 0), hi = make_uint4(0, 0, 0, 0);
            if (rowok && (unsigned)nx < IMG && !first) {
                const uint4* hp = (const uint4*)(hh_prev +
                    ((size_t)((b << 16) + (gy << 8) + nx)) * HID);
                lo = hp[0]; hi = hp[1];
            }
            q[dx * 2]     = lo;
            q[dx * 2 + 1] = hi;
        }
        /* x taps: 15 fp32 loads + cvt into k 48..62 (pad k=63) */
        {
            unsigned short xs[16];
            #pragma unroll
            for (int e = 0; e < 16; ++e) xs[e] = 0;
            #pragma unroll
            for (int dx = 0; dx < 3; ++dx) {
                const int gx = x0 + m - 1 + dx;
                const bool ok = rowok && ((unsigned)gx < IMG);
                #pragma unroll
                for (int ch = 0; ch < 5; ++ch) {
                    if (ok)
                        xs[dx * 5 + ch] = __half_as_ushort(__float2half_rn(
                            xall[(((b * TSTEPS + t) * CIN_X + ch) << 16) + (gy << 8) + gx]));
                }
            }
            uint32_t* xw = (uint32_t*)&q[6];
            #pragma unroll
            for (int e = 0; e < 8; ++e)
                xw[e] = (uint32_t)xs[2 * e] | ((uint32_t)xs[2 * e + 1] << 16);
        }
        #pragma unroll
        for (int qi = 0; qi < 8; ++qi) {
            uint32_t off = (uint32_t)(tid * 128 + qi * 16);
            off ^= (uint32_t)((tid & 7) << 4);
            *(uint4*)(smem + SM_A + off) = q[qi];
        }
    }
    __syncthreads();

    /* ---- mainloop: 12 iters x (4 ldsm + 8 mma) ---- */
    const int wm = wid >> 1;
    const int wn = wid & 1;
    const int m_base = wm * 32;
    const int n_base = wn * 32;
    const int j  = lane >> 3;
    const int rr = lane & 7;

    uint32_t offA[2], offB[2];
    #pragma unroll
    for (int mt = 0; mt < 2; ++mt) {
        const int row = m_base + mt * 16 + (j & 1) * 8 + rr;
        const int c16 = j >> 1;
        offA[mt] = (uint32_t)(row * 128 + ((c16 << 4) ^ ((row & 7) << 4)));
    }
    #pragma unroll
    for (int nb = 0; nb < 2; ++nb) {
        const int row = n_base + nb * 16 + (j >> 1) * 8 + rr;
        const int c16 = j & 1;
        offB[nb] = (uint32_t)(row * 128 + ((c16 << 4) ^ ((row & 7) << 4)));
    }

    float acc[8][4];
    #pragma unroll
    for (int q = 0; q < 8; ++q)
        #pragma unroll
        for (int e = 0; e < 4; ++e) acc[q][e] = 0.0f;

    #pragma unroll
    for (int it = 0; it < 12; ++it) {
        const int dy = it >> 2;
        const uint32_t kx = (uint32_t)((it & 3) << 5);
        const uint32_t Ab = sb + SM_A + (uint32_t)(dy * 16384);
        uint32_t a0[4], a1[4], b0[4], b1[4];
        ldsm4(a0, Ab + (offA[0] ^ kx));
        ldsm4(a1, Ab + (offA[1] ^ kx));
        ldsm4(b0, sb + SM_B(dy) + (offB[0] ^ kx));
        ldsm4(b1, sb + SM_B(dy) + (offB[1] ^ kx));
        mma16816(acc[0], a0, b0[0], b0[1]);
        mma16816(acc[1], a0, b0[2], b0[3]);
        mma16816(acc[2], a0, b1[0], b1[1]);
        mma16816(acc[3], a0, b1[2], b1[3]);
        mma16816(acc[4], a1, b0[0], b0[1]);
        mma16816(acc[5], a1, b0[2], b0[3]);
        mma16816(acc[6], a1, b1[0], b1[1]);
        mma16816(acc[7], a1, b1[2], b1[3]);
    }

    /* ---- direct epilogue from registers (no stage, no extra sync) ----
       acc[mt*4 + nb][e]: pixel row m_base+mt*16+(lane>>2)+(e>>1)*8,
       column n_base + nb*8 + 2*(lane&3) + (e&1).
       Permuted B: that column == gate nb, hid wn*8 + 2*(lane&3) + (e&1). */
    {
        const int g4 = lane >> 2;
        const int q4 = lane & 3;
        const int hid0 = wn * 8 + 2 * q4;   /* even */
        const float bi0 = bc[hid0],      bi1 = bc[hid0 + 1];
        const float bf0 = bc[hid0 + 16], bf1 = bc[hid0 + 17];
        const float bo0 = bc[hid0 + 32], bo1 = bc[hid0 + 33];
        const float bg0 = bc[hid0 + 48], bg1 = bc[hid0 + 49];
        #pragma unroll
        for (int mt = 0; mt < 2; ++mt) {
            #pragma unroll
            for (int hrow = 0; hrow < 2; ++hrow) {
                const int m  = m_base + mt * 16 + g4 + hrow * 8;
                const int e0 = hrow * 2, e1 = hrow * 2 + 1;
                const int pix  = ((y0 + (m >> 7)) << 8) + x0 + (m & 127);
                const int base = ((b << 16) + pix) * HID + hid0;
                float c0o = 0.0f, c1o = 0.0f;
                if (!first) {
                    float2 cc = *(const float2*)(g_c + base);
                    c0o = cc.x; c1o = cc.y;
                }
                const float i0 = sig_(acc[mt * 4 + 0][e0] + bi0);
                const float f0 = sig_(acc[mt * 4 + 1][e0] + bf0);
                const float o0 = sig_(acc[mt * 4 + 2][e0] + bo0);
                const float gg0 = tanh_(acc[mt * 4 + 3][e0] + bg0);
                const float i1 = sig_(acc[mt * 4 + 0][e1] + bi1);
                const float f1 = sig_(acc[mt * 4 + 1][e1] + bf1);
                const float o1 = sig_(acc[mt * 4 + 2][e1] + bo1);
                const float gg1 = tanh_(acc[mt * 4 + 3][e1] + bg1);
                const float c0 = f0 * c0o + i0 * gg0;
                const float c1 = f1 * c1o + i1 * gg1;
                *(float2*)(g_c + base) = make_float2(c0, c1);
                __half2 hv = __floats2half2_rn(o0 * tanh_(c0), o1 * tanh_(c1));
                *(__half2*)(hh_next + base) = hv;
            }
        }
    }
}

/* Final 1x1 conv over [pix][ch] fp16 h_last. 4 px per thread. */
__global__ void final_conv_kernel(const float* __restrict__ Wf,
                                  const float* __restrict__ bfin,
                                  float* __restrict__ out)
{
    const int total4 = BATCH * IMG * IMG / 4;
    int p4 = blockIdx.x * blockDim.x + threadIdx.x;
    if (p4 >= total4) return;
    const __half* h = g_hh[TSTEPS & 1];
    const int b    = p4 >> 14;
    const int pix0 = (p4 & 16383) * 4;
    float w[HID];
    #pragma unroll
    for (int jj = 0; jj < HID; ++jj) w[jj] = Wf[jj];
    const float bv = bfin[0];
    float a[4];
    #pragma unroll
    for (int p = 0; p < 4; ++p) {
        const __half2* hp = (const __half2*)(h + ((size_t)((b << 16) + pix0 + p)) * HID);
        float s = bv;
        #pragma unroll
        for (int q = 0; q < 8; ++q) {
            float2 f2 = __half22float2(hp[q]);
            s += w[2 * q] * f2.x + w[2 * q + 1] * f2.y;
        }
        a[p] = s;
    }
    ((float4*)out)[p4] = make_float4(a[0], a[1], a[2], a[3]);
}

extern "C" void kernel_launch(void* const* d_in, const int* in_sizes, int n_in,
                              void* d_out, int out_size)
{
    const float* x  = (const float*)d_in[0];
    const float* Wc = (const float*)d_in[1];
    const float* bc = (const float*)d_in[2];
    const float* Wf = (const float*)d_in[3];
    const float* bf = (const float*)d_in[4];
    float* out = (float*)d_out;

    cudaFuncSetAttribute(lstm_step_kernel,
                         cudaFuncAttributeMaxDynamicSharedMemorySize, SMEM_TOTAL);

    build_B_kernel<<<1, 192>>>(Wc);

    dim3 grid(IMG / 128, IMG / 2, BATCH);   /* 2048 CTAs */
    for (int t = 0; t < TSTEPS; ++t)
        lstm_step_kernel<<<grid, NTHREADS, SMEM_TOTAL>>>(x, bc, t);

    const int total4 = BATCH * IMG * IMG / 4;
    final_conv_kernel<<<(total4 + 511) / 512, 512>>>(Wf, bf, out);
}